// round 7
// baseline (speedup 1.0000x reference)
#include <cuda_runtime.h>
#include <cuda_bf16.h>
#include <cstdint>

#define BSZ 128
#define DIM 1024
#define NCLS 32768
#define INV_TAU 20.0f
#define THRESH 20.0f
#define NBLK (NCLS / 128)   // 256 gemm blocks
#define BK 32               // k per tile
#define NT (DIM / BK)       // 32 iterations

// Scratch (device globals: no allocations allowed)
__device__ alignas(16) __nv_bfloat16 g_abf[BSZ * DIM];  // bf16 inputs
__device__ alignas(16) float g_pse[BSZ * NBLK];         // partial sumexp(s-20)
__device__ alignas(16) float g_pcn[BSZ * NBLK];         // partial count > 20
__device__ alignas(16) float g_pss[BSZ * NBLK];         // partial sum of s > 20
__device__ alignas(16) float g_st[BSZ];                 // s[target[b]]

// dynamic smem layout (all offsets 16B-aligned)
#define A_OFF 0               // 3 stages x 10240 B (128 rows x 80B: 64B data + pad)
#define B32_OFF 30720         // 3 stages x 16384 B (128 rows x 128B fp32)
#define BB16_OFF 79872        // 2 bufs  x 10240 B (128 rows x 80B bf16)
#define SMEM_DYN 100352

__device__ __forceinline__ unsigned su32(const void* p) {
    return (unsigned)__cvta_generic_to_shared(p);
}
__device__ __forceinline__ uint32_t pack_bf16x2(float lo, float hi) {
    return ((uint32_t)__bfloat16_as_ushort(__float2bfloat16(hi)) << 16) |
           (uint32_t)__bfloat16_as_ushort(__float2bfloat16(lo));
}
__device__ __forceinline__ void cpasync16(uint32_t dst, const void* src) {
    asm volatile("cp.async.cg.shared.global [%0], [%1], 16;"
                 :: "r"(dst), "l"(src) : "memory");
}
__device__ __forceinline__ void mma_bf16(float* c, const uint32_t* a, const uint32_t* b) {
    asm volatile(
        "mma.sync.aligned.m16n8k16.row.col.f32.bf16.bf16.f32 "
        "{%0,%1,%2,%3}, {%4,%5,%6,%7}, {%8,%9}, {%0,%1,%2,%3};\n"
        : "+f"(c[0]), "+f"(c[1]), "+f"(c[2]), "+f"(c[3])
        : "r"(a[0]), "r"(a[1]), "r"(a[2]), "r"(a[3]), "r"(b[0]), "r"(b[1]));
}

// ---------------------------------------------------------------------------
// K0: convert inputs to bf16 once (vectorized)
// ---------------------------------------------------------------------------
__global__ __launch_bounds__(256) void convert_inputs_kernel(const float* __restrict__ in) {
    int i = (blockIdx.x * 256 + threadIdx.x) * 4;
    float4 v = *reinterpret_cast<const float4*>(&in[i]);
    *reinterpret_cast<uint2*>(&g_abf[i]) =
        make_uint2(pack_bf16x2(v.x, v.y), pack_bf16x2(v.z, v.w));
}

// ---------------------------------------------------------------------------
// K1: GEMM (scores = inputs @ em^T * 20) fused with em -> out_em copy and
// softmax statistics. cp.async 3-stage pipeline for A (bf16) and B (fp32);
// staging phase converts fp32->bf16 and emits the out_em copy (scalar STG,
// base is 4 mod 16); mma.sync consumes double-buffered bf16 B tiles and the
// A stage directly.
// ---------------------------------------------------------------------------
__global__ __launch_bounds__(256, 2) void gemm_fused_kernel(const float* __restrict__ em,
                                                            float* __restrict__ out_em,
                                                            const int* __restrict__ targets) {
    extern __shared__ char dsm[];
    __shared__ float sRed[3][BSZ][4];
    __shared__ int sT[BSZ];

    const int tid = threadIdx.x;
    const int warp = tid >> 5;
    const int lane = tid & 31;
    const int warpM = warp >> 2;  // 0..1
    const int warpN = warp & 3;   // 0..3
    const int cBase = blockIdx.x * 128;

    if (tid < BSZ) sT[tid] = targets[tid];

    float acc[4][4][4];
#pragma unroll
    for (int i = 0; i < 4; i++)
#pragma unroll
        for (int j = 0; j < 4; j++)
#pragma unroll
            for (int k = 0; k < 4; k++) acc[i][j][k] = 0.0f;

    // issue cp.async group for tile kt2 into stage kt2%3
    auto issueStage = [&](int kt2) {
        const int s2 = kt2 % 3;
        char* adst = dsm + A_OFF + s2 * 10240;
        char* bdst = dsm + B32_OFF + s2 * 16384;
#pragma unroll
        for (int it = 0; it < 2; it++) {       // A: 512 x 16B chunks
            int c = tid + it * 256;
            int row = c >> 2, q = c & 3;
            cpasync16(su32(adst + row * 80 + q * 16),
                      (const char*)g_abf + row * (DIM * 2) + kt2 * (BK * 2) + q * 16);
        }
#pragma unroll
        for (int it = 0; it < 4; it++) {       // B: 1024 x 16B chunks
            int c = tid + it * 256;
            int row = c >> 3, q = c & 7;
            cpasync16(su32(bdst + row * 128 + q * 16),
                      (const char*)em +
                          ((size_t)(cBase + row) * DIM + kt2 * BK + q * 4) * 4);
        }
        asm volatile("cp.async.commit_group;" ::: "memory");
    };

    issueStage(0);
    issueStage(1);

    for (int kt = 0; kt < NT; kt++) {
        asm volatile("cp.async.wait_group 1;" ::: "memory");
        __syncthreads();

        const int s = kt % 3;
        const int bfb = kt & 1;
        const char* b32s = dsm + B32_OFF + s * 16384;
        char* bb = dsm + BB16_OFF + bfb * 10240;
        const char* as = dsm + A_OFF + s * 10240;

        // ---- staging: fp32 stage -> out_em copy + bf16 tile ----
#pragma unroll
        for (int it = 0; it < 4; it++) {
            int c = tid + it * 256;
            int row = c >> 3, q = c & 7;
            float4 v = *reinterpret_cast<const float4*>(b32s + row * 128 + q * 16);
            size_t gb = (size_t)(cBase + row) * DIM + kt * BK + q * 4;
            out_em[gb + 0] = v.x;
            out_em[gb + 1] = v.y;
            out_em[gb + 2] = v.z;
            out_em[gb + 3] = v.w;
            *reinterpret_cast<uint2*>(bb + row * 80 + q * 8) =
                make_uint2(pack_bf16x2(v.x, v.y), pack_bf16x2(v.z, v.w));
        }
        __syncthreads();

        // ---- mma: A from stage s (bf16), B from bb ----
#pragma unroll
        for (int ks = 0; ks < BK; ks += 16) {
            uint32_t afr[4][4];
            {
                int r = lane & 15;
                int c16 = (lane >> 4) * 16;   // byte offset of 8-col group
#pragma unroll
                for (int i = 0; i < 4; i++) {
                    unsigned addr = su32(as + (warpM * 64 + i * 16 + r) * 80 + ks * 2 + c16);
                    asm volatile(
                        "ldmatrix.sync.aligned.m8n8.x4.shared.b16 {%0,%1,%2,%3}, [%4];"
                        : "=r"(afr[i][0]), "=r"(afr[i][1]), "=r"(afr[i][2]), "=r"(afr[i][3])
                        : "r"(addr));
                }
            }
            uint32_t bfr[4][2];
            {
                int rb8 = lane & 7;
                int cb16 = ((lane >> 3) & 1) * 16;
#pragma unroll
                for (int j = 0; j < 4; j++) {
                    unsigned addr = su32(bb + (warpN * 32 + j * 8 + rb8) * 80 + ks * 2 + cb16);
                    asm volatile(
                        "ldmatrix.sync.aligned.m8n8.x2.shared.b16 {%0,%1}, [%2];"
                        : "=r"(bfr[j][0]), "=r"(bfr[j][1])
                        : "r"(addr));
                }
            }
#pragma unroll
            for (int i = 0; i < 4; i++)
#pragma unroll
                for (int j = 0; j < 4; j++) mma_bf16(acc[i][j], afr[i], bfr[j]);
        }

        if (kt + 2 < NT) {
            issueStage(kt + 2);
        } else {
            asm volatile("cp.async.commit_group;" ::: "memory");  // keep group count
        }
    }

    // ---- fused epilogue: per-row partial statistics ----
    const int r = lane >> 2;
#pragma unroll
    for (int i = 0; i < 4; i++) {
#pragma unroll
        for (int half = 0; half < 2; half++) {
            int bb2 = warpM * 64 + i * 16 + r + half * 8;   // global sample index
            int tgt = sT[bb2];
            float se = 0.0f, cn = 0.0f, ss = 0.0f;
#pragma unroll
            for (int j = 0; j < 4; j++) {
                int cc = cBase + warpN * 32 + j * 8 + (lane & 3) * 2;
                float v0 = acc[i][j][half * 2 + 0] * INV_TAU;
                float v1 = acc[i][j][half * 2 + 1] * INV_TAU;
                se += __expf(v0 - 20.0f) + __expf(v1 - 20.0f);
                if (v0 > THRESH) { cn += 1.0f; ss += v0; }
                if (v1 > THRESH) { cn += 1.0f; ss += v1; }
                if (cc == tgt) g_st[bb2] = v0;
                if (cc + 1 == tgt) g_st[bb2] = v1;
            }
#pragma unroll
            for (int o = 1; o < 4; o <<= 1) {
                se += __shfl_xor_sync(~0u, se, o);
                cn += __shfl_xor_sync(~0u, cn, o);
                ss += __shfl_xor_sync(~0u, ss, o);
            }
            if ((lane & 3) == 0) {
                sRed[0][bb2][warpN] = se;
                sRed[1][bb2][warpN] = cn;
                sRed[2][bb2][warpN] = ss;
            }
        }
    }
    __syncthreads();
    if (tid < BSZ) {
        g_pse[tid * NBLK + blockIdx.x] =
            sRed[0][tid][0] + sRed[0][tid][1] + sRed[0][tid][2] + sRed[0][tid][3];
        g_pcn[tid * NBLK + blockIdx.x] =
            sRed[1][tid][0] + sRed[1][tid][1] + sRed[1][tid][2] + sRed[1][tid][3];
        g_pss[tid * NBLK + blockIdx.x] =
            sRed[2][tid][0] + sRed[2][tid][1] + sRed[2][tid][2] + sRed[2][tid][3];
    }
}

// ---------------------------------------------------------------------------
// K2: fused scatter + loss.
// Blocks 0..127: EMA scatter chains (O(1) head detection via smem + ballot).
// Block 128: reduce partials, write ks and final loss mean.
// ---------------------------------------------------------------------------
__global__ __launch_bounds__(256) void scatter_loss_kernel(const float* __restrict__ inputs,
                                                           const int* __restrict__ targets,
                                                           const int* __restrict__ epoch,
                                                           float* __restrict__ out_em,
                                                           float* __restrict__ out) {
    const int t = threadIdx.x;
    const int warp = t >> 5;
    const int lane = t & 31;

    if (blockIdx.x == BSZ) {
        __shared__ float sLoss[BSZ];
        for (int b = warp; b < BSZ; b += 8) {
            float se = 0.0f, cn = 0.0f, ss = 0.0f;
#pragma unroll
            for (int i = lane; i < NBLK; i += 32) {
                se += g_pse[b * NBLK + i];
                cn += g_pcn[b * NBLK + i];
                ss += g_pss[b * NBLK + i];
            }
#pragma unroll
            for (int o = 16; o; o >>= 1) {
                se += __shfl_xor_sync(~0u, se, o);
                cn += __shfl_xor_sync(~0u, cn, o);
                ss += __shfl_xor_sync(~0u, ss, o);
            }
            if (lane == 0) {
                float st = g_st[b];
                float lse = 20.0f + logf(se);
                float logpt = st - lse;
                int n = (int)(cn + 0.5f);
                float loss;
                if (n > 1) {
                    float kk = 1.0f / ((float)n * logf((float)n));
                    int ta = (st > THRESH) ? 1 : 0;
                    float extra = kk * ((ss - (ta ? st : 0.0f)) - (float)(n - ta) * lse);
                    loss = -(extra + logpt);
                } else {
                    loss = -logpt;
                }
                sLoss[b] = loss;
                out[1 + b] = cn;  // ks
            }
        }
        __syncthreads();
        if (t == 0) {
            float acc = 0.0f;
            for (int i = 0; i < BSZ; i++) acc += sLoss[i];
            out[0] = acc / (float)BSZ;
        }
        return;
    }

    // ---- scatter block ----
    __shared__ int sT[BSZ];
    __shared__ float red[8];
    __shared__ float bc;
    if (t < BSZ) sT[t] = targets[t];
    __syncthreads();

    const int b = blockIdx.x;
    const int y = sT[b];
    int match = (t < b && sT[t] == y) ? 1 : 0;
    if (__syncthreads_or(match)) return;  // not the chain head (uniform)

    const float mu = fminf(0.4f / 60.0f * (float)(epoch[0] + 1), 1.0f);
    const float omu = 1.0f - mu;

    const size_t rbase = (size_t)y * DIM + t * 4;
    float row[4];
#pragma unroll
    for (int q = 0; q < 4; q++) row[q] = out_em[rbase + q];  // scalar: base 4 mod 16

    for (int j = b; j < BSZ; j++) {
        if (sT[j] != y) continue;  // uniform across block (smem)
        float4 x = *reinterpret_cast<const float4*>(&inputs[(size_t)j * DIM + t * 4]);
        float v0 = mu * row[0] + omu * x.x;
        float v1 = mu * row[1] + omu * x.y;
        float v2 = mu * row[2] + omu * x.z;
        float v3 = mu * row[3] + omu * x.w;
        float sq = v0 * v0 + v1 * v1 + v2 * v2 + v3 * v3;
#pragma unroll
        for (int o = 16; o; o >>= 1) sq += __shfl_xor_sync(~0u, sq, o);
        if (lane == 0) red[warp] = sq;
        __syncthreads();
        if (t == 0) {
            float s = 0.0f;
#pragma unroll
            for (int i = 0; i < 8; i++) s += red[i];
            bc = s;
        }
        __syncthreads();
        float rn = rsqrtf(bc);
        row[0] = v0 * rn; row[1] = v1 * rn; row[2] = v2 * rn; row[3] = v3 * rn;
    }
#pragma unroll
    for (int q = 0; q < 4; q++) out_em[rbase + q] = row[q];
}

// ---------------------------------------------------------------------------
// Entry point. Output layout (float32): [loss(1), ks(128), new_em(32768*1024)]
// ---------------------------------------------------------------------------
extern "C" void kernel_launch(void* const* d_in, const int* in_sizes, int n_in,
                              void* d_out, int out_size) {
    const float* inputs = (const float*)d_in[0];
    const float* em = (const float*)d_in[1];
    const int* targets = (const int*)d_in[2];
    const int* epoch = (const int*)d_in[3];
    float* out = (float*)d_out;
    float* out_em = out + 1 + BSZ;

    static bool attr_set = false;
    if (!attr_set) {
        cudaFuncSetAttribute(gemm_fused_kernel,
                             cudaFuncAttributeMaxDynamicSharedMemorySize, SMEM_DYN);
        attr_set = true;
    }

    convert_inputs_kernel<<<128, 256>>>(inputs);
    gemm_fused_kernel<<<NBLK, 256, SMEM_DYN>>>(em, out_em, targets);
    scatter_loss_kernel<<<BSZ + 1, 256>>>(inputs, targets, epoch, out_em, out);
}

// round 8
// speedup vs baseline: 1.0685x; 1.0685x over previous
#include <cuda_runtime.h>
#include <cuda_bf16.h>
#include <cstdint>

#define BSZ 128
#define DIM 1024
#define NCLS 32768
#define INV_TAU 20.0f
#define THRESH 20.0f
#define NBLK (NCLS / 128)   // 256 gemm blocks
#define BK 32               // k per tile
#define NT (DIM / BK)       // 32 iterations

// Scratch (device globals: no allocations allowed)
__device__ alignas(16) __nv_bfloat16 g_abf[BSZ * DIM];  // bf16 inputs
__device__ alignas(16) float g_pse[BSZ * NBLK];         // partial sumexp(s-20)
__device__ alignas(16) float g_pcn[BSZ * NBLK];         // partial count > 20
__device__ alignas(16) float g_pss[BSZ * NBLK];         // partial sum of s > 20
__device__ alignas(16) float g_st[BSZ];                 // s[target[b]]

// dynamic smem: A ring (cp.async) 3 x 10240 B (128 rows x 80B), then
// B bf16 double buffer 2 x 10240 B (128 rows x 80B)
#define A_OFF 0
#define B_OFF 30720
#define SMEM_DYN 51200

__device__ __forceinline__ unsigned su32(const void* p) {
    return (unsigned)__cvta_generic_to_shared(p);
}
__device__ __forceinline__ uint32_t pack_bf16x2(float lo, float hi) {
    return ((uint32_t)__bfloat16_as_ushort(__float2bfloat16(hi)) << 16) |
           (uint32_t)__bfloat16_as_ushort(__float2bfloat16(lo));
}
__device__ __forceinline__ void cpasync16(uint32_t dst, const void* src) {
    asm volatile("cp.async.cg.shared.global [%0], [%1], 16;"
                 :: "r"(dst), "l"(src) : "memory");
}
__device__ __forceinline__ void mma_bf16(float* c, const uint32_t* a, const uint32_t* b) {
    asm volatile(
        "mma.sync.aligned.m16n8k16.row.col.f32.bf16.bf16.f32 "
        "{%0,%1,%2,%3}, {%4,%5,%6,%7}, {%8,%9}, {%0,%1,%2,%3};\n"
        : "+f"(c[0]), "+f"(c[1]), "+f"(c[2]), "+f"(c[3])
        : "r"(a[0]), "r"(a[1]), "r"(a[2]), "r"(a[3]), "r"(b[0]), "r"(b[1]));
}

// ---------------------------------------------------------------------------
// K0: convert inputs to bf16 once (vectorized)
// ---------------------------------------------------------------------------
__global__ __launch_bounds__(256) void convert_inputs_kernel(const float* __restrict__ in) {
    int i = (blockIdx.x * 256 + threadIdx.x) * 4;
    float4 v = *reinterpret_cast<const float4*>(&in[i]);
    *reinterpret_cast<uint2*>(&g_abf[i]) =
        make_uint2(pack_bf16x2(v.x, v.y), pack_bf16x2(v.z, v.w));
}

// ---------------------------------------------------------------------------
// K1: GEMM (scores = inputs @ em^T * 20) fused with em -> out_em copy and
// softmax statistics.
//   A: cp.async bf16 ring (3 stages), zero register cost, ldmatrix direct.
//   B: LDG.128 (streaming) -> regs -> {STG out_em copy, STS bf16} (R4 path).
//   One barrier per K-iter; B double-buffered.
// ---------------------------------------------------------------------------
__global__ __launch_bounds__(256, 2) void gemm_fused_kernel(const float* __restrict__ em,
                                                            float* __restrict__ out_em,
                                                            const int* __restrict__ targets) {
    extern __shared__ char dsm[];
    __shared__ float sRed[3][BSZ][4];
    __shared__ int sT[BSZ];

    const int tid = threadIdx.x;
    const int warp = tid >> 5;
    const int lane = tid & 31;
    const int warpM = warp >> 2;  // 0..1
    const int warpN = warp & 3;   // 0..3
    const int cBase = blockIdx.x * 128;

    if (tid < BSZ) sT[tid] = targets[tid];

    float acc[4][4][4];
#pragma unroll
    for (int i = 0; i < 4; i++)
#pragma unroll
        for (int j = 0; j < 4; j++)
#pragma unroll
            for (int k = 0; k < 4; k++) acc[i][j][k] = 0.0f;

    // ---- A via cp.async: tile kt -> stage kt%3 (512 x 16B chunks) ----
    auto issueA = [&](int kt2) {
        const int s2 = kt2 % 3;
        char* adst = dsm + A_OFF + s2 * 10240;
#pragma unroll
        for (int it = 0; it < 2; it++) {
            int c = tid + it * 256;
            int row = c >> 2, q = c & 3;
            cpasync16(su32(adst + row * 80 + q * 16),
                      (const char*)g_abf + row * (DIM * 2) + kt2 * (BK * 2) + q * 16);
        }
        asm volatile("cp.async.commit_group;" ::: "memory");
    };

    // ---- B: LDG into regs / stage regs -> out_em + bf16 smem ----
    float4 rbv[4];
    auto loadB = [&](int kt2) {
#pragma unroll
        for (int it = 0; it < 4; it++) {
            int c = tid + it * 256;
            int row = c >> 3, col4 = (c & 7) * 4;
            rbv[it] = __ldcs(reinterpret_cast<const float4*>(
                &em[(size_t)(cBase + row) * DIM + kt2 * BK + col4]));
        }
    };
    auto stageB = [&](int kt2, char* bdst) {
#pragma unroll
        for (int it = 0; it < 4; it++) {
            int c = tid + it * 256;
            int row = c >> 3, col4 = (c & 7) * 4;
            size_t gb = (size_t)(cBase + row) * DIM + kt2 * BK + col4;
            float4 v = rbv[it];
            __stcs(&out_em[gb], v.x);                                  // addr 4 mod 16
            __stcs(reinterpret_cast<float2*>(&out_em[gb + 1]),
                   make_float2(v.y, v.z));                             // addr 8 mod 16
            __stcs(&out_em[gb + 3], v.w);
            *reinterpret_cast<uint2*>(bdst + row * 80 + col4 * 2) =
                make_uint2(pack_bf16x2(v.x, v.y), pack_bf16x2(v.z, v.w));
        }
    };

    // ---- prologue ----
    issueA(0);
    issueA(1);
    loadB(0);
    stageB(0, dsm + B_OFF);
    asm volatile("cp.async.wait_group 1;" ::: "memory");
    __syncthreads();

    for (int kt = 0; kt < NT; kt++) {
        const int as_ = kt % 3;
        const int bcur = kt & 1;
        const char* as = dsm + A_OFF + as_ * 10240;
        const char* bb = dsm + B_OFF + bcur * 10240;
        const bool more = (kt + 1 < NT);

        if (more) loadB(kt + 1);
        if (kt + 2 < NT) issueA(kt + 2);
        else asm volatile("cp.async.commit_group;" ::: "memory");  // keep group count

        // ---- MMA over 2 k-steps of 16 ----
#pragma unroll
        for (int ks = 0; ks < BK; ks += 16) {
            uint32_t afr[4][4];
            {
                int r = lane & 15;
                int c16 = (lane >> 4) * 16;
#pragma unroll
                for (int i = 0; i < 4; i++) {
                    unsigned addr = su32(as + (warpM * 64 + i * 16 + r) * 80 + ks * 2 + c16);
                    asm volatile(
                        "ldmatrix.sync.aligned.m8n8.x4.shared.b16 {%0,%1,%2,%3}, [%4];"
                        : "=r"(afr[i][0]), "=r"(afr[i][1]), "=r"(afr[i][2]), "=r"(afr[i][3])
                        : "r"(addr));
                }
            }
            uint32_t bfr[4][2];
            {
                int rb8 = lane & 7;
                int cb16 = ((lane >> 3) & 1) * 16;
#pragma unroll
                for (int j = 0; j < 4; j++) {
                    unsigned addr = su32(bb + (warpN * 32 + j * 8 + rb8) * 80 + ks * 2 + cb16);
                    asm volatile(
                        "ldmatrix.sync.aligned.m8n8.x2.shared.b16 {%0,%1}, [%2];"
                        : "=r"(bfr[j][0]), "=r"(bfr[j][1])
                        : "r"(addr));
                }
            }
#pragma unroll
            for (int i = 0; i < 4; i++)
#pragma unroll
                for (int j = 0; j < 4; j++) mma_bf16(acc[i][j], afr[i], bfr[j]);
        }

        if (more) stageB(kt + 1, dsm + B_OFF + (bcur ^ 1) * 10240);
        asm volatile("cp.async.wait_group 1;" ::: "memory");
        __syncthreads();
    }

    // ---- fused epilogue: per-row partial statistics ----
    const int r = lane >> 2;
#pragma unroll
    for (int i = 0; i < 4; i++) {
#pragma unroll
        for (int half = 0; half < 2; half++) {
            int bb2 = warpM * 64 + i * 16 + r + half * 8;   // global sample index
            int tgt = sT[bb2];
            float se = 0.0f, cn = 0.0f, ss = 0.0f;
#pragma unroll
            for (int j = 0; j < 4; j++) {
                int cc = cBase + warpN * 32 + j * 8 + (lane & 3) * 2;
                float v0 = acc[i][j][half * 2 + 0] * INV_TAU;
                float v1 = acc[i][j][half * 2 + 1] * INV_TAU;
                se += __expf(v0 - 20.0f) + __expf(v1 - 20.0f);
                if (v0 > THRESH) { cn += 1.0f; ss += v0; }
                if (v1 > THRESH) { cn += 1.0f; ss += v1; }
                if (cc == tgt) g_st[bb2] = v0;
                if (cc + 1 == tgt) g_st[bb2] = v1;
            }
#pragma unroll
            for (int o = 1; o < 4; o <<= 1) {
                se += __shfl_xor_sync(~0u, se, o);
                cn += __shfl_xor_sync(~0u, cn, o);
                ss += __shfl_xor_sync(~0u, ss, o);
            }
            if ((lane & 3) == 0) {
                sRed[0][bb2][warpN] = se;
                sRed[1][bb2][warpN] = cn;
                sRed[2][bb2][warpN] = ss;
            }
        }
    }
    __syncthreads();
    if (tid < BSZ) {
        g_pse[tid * NBLK + blockIdx.x] =
            sRed[0][tid][0] + sRed[0][tid][1] + sRed[0][tid][2] + sRed[0][tid][3];
        g_pcn[tid * NBLK + blockIdx.x] =
            sRed[1][tid][0] + sRed[1][tid][1] + sRed[1][tid][2] + sRed[1][tid][3];
        g_pss[tid * NBLK + blockIdx.x] =
            sRed[2][tid][0] + sRed[2][tid][1] + sRed[2][tid][2] + sRed[2][tid][3];
    }
}

// ---------------------------------------------------------------------------
// K2: fused scatter + loss.
// Blocks 0..127: EMA scatter chains (O(1) head detection via smem + ballot).
// Block 128: reduce partials, write ks and final loss mean.
// ---------------------------------------------------------------------------
__global__ __launch_bounds__(256) void scatter_loss_kernel(const float* __restrict__ inputs,
                                                           const int* __restrict__ targets,
                                                           const int* __restrict__ epoch,
                                                           float* __restrict__ out_em,
                                                           float* __restrict__ out) {
    const int t = threadIdx.x;
    const int warp = t >> 5;
    const int lane = t & 31;

    if (blockIdx.x == BSZ) {
        __shared__ float sLoss[BSZ];
        for (int b = warp; b < BSZ; b += 8) {
            float se = 0.0f, cn = 0.0f, ss = 0.0f;
#pragma unroll
            for (int i = lane; i < NBLK; i += 32) {
                se += g_pse[b * NBLK + i];
                cn += g_pcn[b * NBLK + i];
                ss += g_pss[b * NBLK + i];
            }
#pragma unroll
            for (int o = 16; o; o >>= 1) {
                se += __shfl_xor_sync(~0u, se, o);
                cn += __shfl_xor_sync(~0u, cn, o);
                ss += __shfl_xor_sync(~0u, ss, o);
            }
            if (lane == 0) {
                float st = g_st[b];
                float lse = 20.0f + logf(se);
                float logpt = st - lse;
                int n = (int)(cn + 0.5f);
                float loss;
                if (n > 1) {
                    float kk = 1.0f / ((float)n * logf((float)n));
                    int ta = (st > THRESH) ? 1 : 0;
                    float extra = kk * ((ss - (ta ? st : 0.0f)) - (float)(n - ta) * lse);
                    loss = -(extra + logpt);
                } else {
                    loss = -logpt;
                }
                sLoss[b] = loss;
                out[1 + b] = cn;  // ks
            }
        }
        __syncthreads();
        if (t == 0) {
            float acc = 0.0f;
            for (int i = 0; i < BSZ; i++) acc += sLoss[i];
            out[0] = acc / (float)BSZ;
        }
        return;
    }

    // ---- scatter block ----
    __shared__ int sT[BSZ];
    __shared__ float red[8];
    __shared__ float bc;
    if (t < BSZ) sT[t] = targets[t];
    __syncthreads();

    const int b = blockIdx.x;
    const int y = sT[b];
    int match = (t < b && sT[t] == y) ? 1 : 0;
    if (__syncthreads_or(match)) return;  // not the chain head (uniform)

    const float mu = fminf(0.4f / 60.0f * (float)(epoch[0] + 1), 1.0f);
    const float omu = 1.0f - mu;

    const size_t rbase = (size_t)y * DIM + t * 4;
    float row[4];
#pragma unroll
    for (int q = 0; q < 4; q++) row[q] = out_em[rbase + q];  // scalar: base 4 mod 16

    for (int j = b; j < BSZ; j++) {
        if (sT[j] != y) continue;  // uniform across block (smem)
        float4 x = *reinterpret_cast<const float4*>(&inputs[(size_t)j * DIM + t * 4]);
        float v0 = mu * row[0] + omu * x.x;
        float v1 = mu * row[1] + omu * x.y;
        float v2 = mu * row[2] + omu * x.z;
        float v3 = mu * row[3] + omu * x.w;
        float sq = v0 * v0 + v1 * v1 + v2 * v2 + v3 * v3;
#pragma unroll
        for (int o = 16; o; o >>= 1) sq += __shfl_xor_sync(~0u, sq, o);
        if (lane == 0) red[warp] = sq;
        __syncthreads();
        if (t == 0) {
            float s = 0.0f;
#pragma unroll
            for (int i = 0; i < 8; i++) s += red[i];
            bc = s;
        }
        __syncthreads();
        float rn = rsqrtf(bc);
        row[0] = v0 * rn; row[1] = v1 * rn; row[2] = v2 * rn; row[3] = v3 * rn;
    }
#pragma unroll
    for (int q = 0; q < 4; q++) out_em[rbase + q] = row[q];
}

// ---------------------------------------------------------------------------
// Entry point. Output layout (float32): [loss(1), ks(128), new_em(32768*1024)]
// ---------------------------------------------------------------------------
extern "C" void kernel_launch(void* const* d_in, const int* in_sizes, int n_in,
                              void* d_out, int out_size) {
    const float* inputs = (const float*)d_in[0];
    const float* em = (const float*)d_in[1];
    const int* targets = (const int*)d_in[2];
    const int* epoch = (const int*)d_in[3];
    float* out = (float*)d_out;
    float* out_em = out + 1 + BSZ;

    static bool attr_set = false;
    if (!attr_set) {
        cudaFuncSetAttribute(gemm_fused_kernel,
                             cudaFuncAttributeMaxDynamicSharedMemorySize, SMEM_DYN);
        attr_set = true;
    }

    convert_inputs_kernel<<<128, 256>>>(inputs);
    gemm_fused_kernel<<<NBLK, 256, SMEM_DYN>>>(em, out_em, targets);
    scatter_loss_kernel<<<BSZ + 1, 256>>>(inputs, targets, epoch, out_em, out);
}